// round 1
// baseline (speedup 1.0000x reference)
#include <cuda_runtime.h>
#include <cuda_bf16.h>
#include <math.h>

#define NN 512
#define CC 32
#define RR 32
#define BT 8      // neighbor tile
#define NT 256    // threads per block
#define EPSF 1e-8f

struct Params {
    const float* in0;   // [N,C,1]
    const float* in1;   // [N,C,3]
    const float* in2;   // [N,C,5]
    const float* rbf;   // [N,N,R]
    const float* rij;   // [N,N,3]
    const float* w1[5]; // [R,R]  (row = hidden j, col = r)
    const float* b1[5]; // [R]
    const float* w2[5]; // [C,R]  (row = out c, col = h)
    const float* b2[5]; // [C]
    float* out;
};

// shared layout (floats)
//  w1s   : 5*1024   @ 0       stored transposed: w1s[f*1024 + r*32 + j]
//  w2s   : 5*1024   @ 5120    stored transposed: w2s[f*1024 + h*32 + c]
//  b1s   : 5*32     @ 10240
//  b2s   : 5*32     @ 10400
//  rbf_s : 8*32     @ 10560
//  hid_s : 8*160    @ 10816
//  rad_s : 8*160    @ 12096
//  geo_s : 8*9      @ 13376   (u0,u1,u2, y0..y4, mask)
//  red_s : 8*32*21  @ 13448
#define SMEM_FLOATS (13448 + 8*32*21)

__global__ __launch_bounds__(NT) void tfn_kernel(Params p) {
    extern __shared__ float smem[];
    float* w1s   = smem;
    float* w2s   = smem + 5120;
    float* b1s   = smem + 10240;
    float* b2s   = smem + 10400;
    float* rbf_s = smem + 10560;
    float* hid_s = smem + 10816;
    float* rad_s = smem + 12096;
    float* geo_s = smem + 13376;
    float* red_s = smem + 13448;

    const int tid  = threadIdx.x;
    const int lane = tid & 31;
    const int w    = tid >> 5;   // warp id 0..7
    const int a    = blockIdx.x;

    // ---- stage weights into shared (transposed for conflict-free reads) ----
    #pragma unroll
    for (int f = 0; f < 5; f++) {
        const float* g1 = p.w1[f];
        const float* g2 = p.w2[f];
        for (int i = tid; i < RR * RR; i += NT) {
            int row = i >> 5;      // j (hidden) for w1, c (out) for w2
            int col = i & 31;      // r for w1, h for w2
            w1s[f * 1024 + col * 32 + row] = g1[i];
            w2s[f * 1024 + col * 32 + row] = g2[i];
        }
        if (tid < 32) {
            b1s[f * 32 + tid] = p.b1[f][tid];
            b2s[f * 32 + tid] = p.b2[f][tid];
        }
    }
    __syncthreads();

    // 21 per-(a,c) accumulators, this thread owns channel c=lane for bt=w
    float acc[21];
    #pragma unroll
    for (int k = 0; k < 21; k++) acc[k] = 0.f;

    const float inv_c2 = 1.0f / (2.0f * 1.7320508075688772f);  // 1/(2*sqrt(3))

    for (int b0 = 0; b0 < NN; b0 += BT) {
        // load rbf tile: 8 rows x 32 = 256 contiguous floats
        rbf_s[tid] = p.rbf[((size_t)a * NN + b0) * RR + tid];

        // geometry for the 8 neighbors (threads 0..7)
        if (tid < BT) {
            int b = b0 + tid;
            const float* rp = p.rij + ((size_t)a * NN + b) * 3;
            float rx = rp[0], ry = rp[1], rz = rp[2];
            float n2  = rx * rx + ry * ry + rz * rz;
            float nrm = sqrtf(n2);
            float invn = 1.0f / (nrm + EPSF);
            float mask = (nrm >= EPSF) ? 1.0f : 0.0f;
            float r2  = fmaxf(n2, EPSF);
            float ir2 = 1.0f / r2;
            float* g = geo_s + tid * 9;
            g[0] = rx * invn;
            g[1] = ry * invn;
            g[2] = rz * invn;
            g[3] = rx * ry * ir2;
            g[4] = ry * rz * ir2;
            g[5] = (-rx * rx - ry * ry + 2.0f * rz * rz) * ir2 * inv_c2;
            g[6] = rz * rx * ir2;
            g[7] = (rx * rx - ry * ry) * 0.5f * ir2;
            g[8] = mask;
        }
        __syncthreads();

        // ---- stage 1: hidden = relu(b1 + w1 @ rbf), 8*5*32 = 1280 dots ----
        #pragma unroll
        for (int pass = 0; pass < 5; pass++) {
            int it  = tid + pass * NT;
            int bt  = it / 160;
            int rem = it - bt * 160;
            int f   = rem >> 5;
            int j   = rem & 31;
            const float* wr = w1s + f * 1024 + j;   // stride 32 over r
            const float* x  = rbf_s + bt * 32;
            float s = b1s[f * 32 + j];
            #pragma unroll
            for (int r = 0; r < 32; r++) s = fmaf(wr[r * 32], x[r], s);
            hid_s[bt * 160 + f * 32 + j] = fmaxf(s, 0.f);
        }
        __syncthreads();

        // ---- stage 2: rad = b2 + w2 @ hidden ----
        #pragma unroll
        for (int pass = 0; pass < 5; pass++) {
            int it  = tid + pass * NT;
            int bt  = it / 160;
            int rem = it - bt * 160;
            int f   = rem >> 5;
            int c   = rem & 31;
            const float* wr = w2s + f * 1024 + c;   // stride 32 over h
            const float* h  = hid_s + bt * 160 + f * 32;
            float s = b2s[f * 32 + c];
            #pragma unroll
            for (int hh = 0; hh < 32; hh++) s = fmaf(wr[hh * 32], h[hh], s);
            rad_s[bt * 160 + f * 32 + c] = s;
        }
        __syncthreads();

        // ---- accumulate: warp w handles neighbor b0+w, lane = channel c ----
        {
            int b = b0 + w;
            int c = lane;
            const float* g = geo_s + w * 9;
            float ux = g[0], uy = g[1], uz = g[2];
            float y0 = g[3], y1 = g[4], y2c = g[5], y3 = g[6], y4 = g[7];
            float mask = g[8];

            const float* rs = rad_s + w * 160;
            float r00 = rs[0 * 32 + c];
            float r01 = rs[1 * 32 + c] * mask;
            float r02 = rs[2 * 32 + c] * mask;
            float r10 = rs[3 * 32 + c] * mask;
            float r11 = rs[4 * 32 + c] * mask;

            float x0 = p.in0[b * CC + c];
            const float* v = p.in1 + ((size_t)b * CC + c) * 3;
            float v0 = v[0], v1 = v[1], v2 = v[2];
            const float* q = p.in2 + ((size_t)b * CC + c) * 5;

            // o0_s, o0_b
            acc[0] = fmaf(r00, x0, acc[0]);
            acc[1] = fmaf(r10, ux * v0 + uy * v1 + uz * v2, acc[1]);
            // o1_a = r01 * u * x0
            float r01x = r01 * x0;
            acc[2] = fmaf(r01x, ux, acc[2]);
            acc[3] = fmaf(r01x, uy, acc[3]);
            acc[4] = fmaf(r01x, uz, acc[4]);
            // o1_s = r00 * in1
            acc[5] = fmaf(r00, v0, acc[5]);
            acc[6] = fmaf(r00, v1, acc[6]);
            acc[7] = fmaf(r00, v2, acc[7]);
            // o1_c = r11 * (u x v)
            acc[8]  = fmaf(r11, uy * v2 - uz * v1, acc[8]);
            acc[9]  = fmaf(r11, uz * v0 - ux * v2, acc[9]);
            acc[10] = fmaf(r11, ux * v1 - uy * v0, acc[10]);
            // o2_a = r02 * y2 * x0
            float r02x = r02 * x0;
            acc[11] = fmaf(r02x, y0, acc[11]);
            acc[12] = fmaf(r02x, y1, acc[12]);
            acc[13] = fmaf(r02x, y2c, acc[13]);
            acc[14] = fmaf(r02x, y3, acc[14]);
            acc[15] = fmaf(r02x, y4, acc[15]);
            // o2_s = r00 * in2
            acc[16] = fmaf(r00, q[0], acc[16]);
            acc[17] = fmaf(r00, q[1], acc[17]);
            acc[18] = fmaf(r00, q[2], acc[18]);
            acc[19] = fmaf(r00, q[3], acc[19]);
            acc[20] = fmaf(r00, q[4], acc[20]);
        }
        __syncthreads();   // protect rbf_s/hid_s/rad_s/geo_s for next tile
    }

    // ---- cross-warp reduction ----
    #pragma unroll
    for (int k = 0; k < 21; k++) red_s[w * 672 + lane * 21 + k] = acc[k];
    __syncthreads();

    // 672 (c,k) items, each sums 8 warps, then writes to global
    for (int item = tid; item < CC * 21; item += NT) {
        int c = item / 21;
        int k = item - c * 21;
        float s = 0.f;
        #pragma unroll
        for (int ww = 0; ww < 8; ww++) s += red_s[ww * 672 + c * 21 + k];

        float* out = p.out;
        size_t idx;
        if (k == 0) {                       // o0_s  [0,a,c,1]
            idx = ((size_t)a) * 32 + c;
        } else if (k == 1) {                // o0_b  [1,a,c,1]
            idx = ((size_t)(NN + a)) * 32 + c;
        } else if (k < 5) {                 // o1_a  i=k-2
            idx = 32768 + (((size_t)a) * 32 + c) * 3 + (k - 2);
        } else if (k < 8) {                 // o1_s
            idx = 32768 + (((size_t)(NN + a)) * 32 + c) * 3 + (k - 5);
        } else if (k < 11) {                // o1_c
            idx = 32768 + (((size_t)(2 * NN + a)) * 32 + c) * 3 + (k - 8);
        } else if (k < 16) {                // o2_a
            idx = 180224 + (((size_t)a) * 32 + c) * 5 + (k - 11);
        } else {                            // o2_s
            idx = 180224 + (((size_t)(NN + a)) * 32 + c) * 5 + (k - 16);
        }
        out[idx] = s;
    }
}

extern "C" void kernel_launch(void* const* d_in, const int* in_sizes, int n_in,
                              void* d_out, int out_size) {
    Params p;
    p.in0 = (const float*)d_in[0];
    p.in1 = (const float*)d_in[1];
    p.in2 = (const float*)d_in[2];
    p.rbf = (const float*)d_in[3];
    p.rij = (const float*)d_in[4];
    for (int f = 0; f < 5; f++) {
        p.w1[f] = (const float*)d_in[5 + 4 * f];
        p.b1[f] = (const float*)d_in[6 + 4 * f];
        p.w2[f] = (const float*)d_in[7 + 4 * f];
        p.b2[f] = (const float*)d_in[8 + 4 * f];
    }
    p.out = (float*)d_out;

    static bool attr_set = false;
    size_t smem_bytes = SMEM_FLOATS * sizeof(float);
    if (!attr_set) {
        cudaFuncSetAttribute(tfn_kernel, cudaFuncAttributeMaxDynamicSharedMemorySize,
                             (int)smem_bytes);
        attr_set = true;
    }
    tfn_kernel<<<NN, NT, smem_bytes>>>(p);
}

// round 3
// speedup vs baseline: 2.2459x; 2.2459x over previous
#include <cuda_runtime.h>
#include <cuda_bf16.h>
#include <math.h>

#define NNODES 512
#define EPSF 1e-8f

struct Params {
    const float* __restrict__ in0;   // [N,C,1]
    const float* __restrict__ in1;   // [N,C,3]
    const float* __restrict__ in2;   // [N,C,5]
    const float* __restrict__ rbf;   // [N,N,R]
    const float* __restrict__ rij;   // [N,N,3]
    const float* __restrict__ w1[5]; // [R,R] row h, col r
    const float* __restrict__ b1[5]; // [R]
    const float* __restrict__ w2[5]; // [C,R] row c, col h
    const float* __restrict__ b2[5]; // [C]
    float* __restrict__ out;
};

// 5 warps = 5 filters. lane j owns row j of w1_f, lane c owns row c of w2_f.
// Per 8-neighbor tile: stage1 hidden -> smem, stage2 rad -> smem,
// then each warp accumulates one group of output components over all 8 neighbors.
__global__ __launch_bounds__(160) void tfn_kernel(Params p) {
    __shared__ float rbf_s[8 * 32];    // [b][r]
    __shared__ float hid_s[8 * 160];   // [b][f*32+j]
    __shared__ float rad_s[8 * 160];   // [b][f*32+c]
    __shared__ float geo_s[8 * 9];     // [b][ux,uy,uz,y0..y4,mask]

    const int tid  = threadIdx.x;
    const int lane = tid & 31;
    const int f    = tid >> 5;          // warp id == filter id (0..4)
    const int a    = blockIdx.x;

    // ---- weights into registers ----
    float w1r[32], w2r[32];
    {
        const float4* w1p = (const float4*)(p.w1[f] + lane * 32);
        const float4* w2p = (const float4*)(p.w2[f] + lane * 32);
        #pragma unroll
        for (int k = 0; k < 8; k++) {
            float4 t1 = w1p[k];
            float4 t2 = w2p[k];
            w1r[4*k+0] = t1.x; w1r[4*k+1] = t1.y; w1r[4*k+2] = t1.z; w1r[4*k+3] = t1.w;
            w2r[4*k+0] = t2.x; w2r[4*k+1] = t2.y; w2r[4*k+2] = t2.z; w2r[4*k+3] = t2.w;
        }
    }
    const float b1r = p.b1[f][lane];
    const float b2r = p.b2[f][lane];

    float acc0 = 0.f, acc1 = 0.f, acc2 = 0.f, acc3 = 0.f, acc4 = 0.f;
    const float inv_c2 = 0.28867513459481287f;  // 1/(2*sqrt(3))
    const int c = lane;

    for (int b0 = 0; b0 < NNODES; b0 += 8) {
        __syncthreads();  // previous tile's accumulate done reading smem

        if (tid < 64) {
            ((float4*)rbf_s)[tid] =
                ((const float4*)(p.rbf + ((size_t)a * NNODES + b0) * 32))[tid];
        } else if (tid < 72) {
            int n = tid - 64;
            const float* rp = p.rij + ((size_t)a * NNODES + b0 + n) * 3;
            float rx = rp[0], ry = rp[1], rz = rp[2];
            float n2 = rx * rx + ry * ry + rz * rz;
            float nrm = sqrtf(n2);
            float invn = 1.f / (nrm + EPSF);
            float mask = (nrm >= EPSF) ? 1.f : 0.f;
            float ir2 = 1.f / fmaxf(n2, EPSF);
            float* g = geo_s + n * 9;
            g[0] = rx * invn; g[1] = ry * invn; g[2] = rz * invn;
            g[3] = rx * ry * ir2;
            g[4] = ry * rz * ir2;
            g[5] = (2.f * rz * rz - rx * rx - ry * ry) * ir2 * inv_c2;
            g[6] = rz * rx * ir2;
            g[7] = (rx * rx - ry * ry) * 0.5f * ir2;
            g[8] = mask;
        }
        __syncthreads();

        // ---- stage1: hidden = relu(b1 + W1 @ rbf)  (weights in regs, x broadcast LDS.128)
        #pragma unroll 4
        for (int b = 0; b < 8; b++) {
            float s = b1r;
            const float4* x4 = (const float4*)(rbf_s + b * 32);
            #pragma unroll
            for (int k = 0; k < 8; k++) {
                float4 x = x4[k];
                s = fmaf(w1r[4*k+0], x.x, s);
                s = fmaf(w1r[4*k+1], x.y, s);
                s = fmaf(w1r[4*k+2], x.z, s);
                s = fmaf(w1r[4*k+3], x.w, s);
            }
            hid_s[b * 160 + f * 32 + lane] = fmaxf(s, 0.f);
        }
        __syncthreads();

        // ---- stage2: rad = b2 + W2 @ hidden
        #pragma unroll 4
        for (int b = 0; b < 8; b++) {
            float s = b2r;
            const float4* h4 = (const float4*)(hid_s + b * 160 + f * 32);
            #pragma unroll
            for (int k = 0; k < 8; k++) {
                float4 x = h4[k];
                s = fmaf(w2r[4*k+0], x.x, s);
                s = fmaf(w2r[4*k+1], x.y, s);
                s = fmaf(w2r[4*k+2], x.z, s);
                s = fmaf(w2r[4*k+3], x.w, s);
            }
            rad_s[b * 160 + f * 32 + lane] = s;
        }
        __syncthreads();

        // ---- accumulate: each warp owns one output group, loops all 8 neighbors
        if (f == 0) {
            // o2_s += r00 * in2
            #pragma unroll 2
            for (int b = 0; b < 8; b++) {
                float r00 = rad_s[b * 160 + c];
                const float* q = p.in2 + ((size_t)(b0 + b) * 32 + c) * 5;
                acc0 = fmaf(r00, q[0], acc0);
                acc1 = fmaf(r00, q[1], acc1);
                acc2 = fmaf(r00, q[2], acc2);
                acc3 = fmaf(r00, q[3], acc3);
                acc4 = fmaf(r00, q[4], acc4);
            }
        } else if (f == 1) {
            // o2_a += (r02*mask) * y2 * x0
            #pragma unroll 2
            for (int b = 0; b < 8; b++) {
                const float* g = geo_s + b * 9;
                float r02 = rad_s[b * 160 + 64 + c] * g[8];
                float x0 = p.in0[(size_t)(b0 + b) * 32 + c];
                float rx = r02 * x0;
                acc0 = fmaf(rx, g[3], acc0);
                acc1 = fmaf(rx, g[4], acc1);
                acc2 = fmaf(rx, g[5], acc2);
                acc3 = fmaf(rx, g[6], acc3);
                acc4 = fmaf(rx, g[7], acc4);
            }
        } else if (f == 2) {
            // o1_s += r00 * in1 ; o0_s += r00 * in0
            #pragma unroll 2
            for (int b = 0; b < 8; b++) {
                float r00 = rad_s[b * 160 + c];
                const float* v = p.in1 + ((size_t)(b0 + b) * 32 + c) * 3;
                acc0 = fmaf(r00, v[0], acc0);
                acc1 = fmaf(r00, v[1], acc1);
                acc2 = fmaf(r00, v[2], acc2);
                acc3 = fmaf(r00, p.in0[(size_t)(b0 + b) * 32 + c], acc3);
            }
        } else if (f == 3) {
            // o1_c += (r11*mask)*(u x v) ; o0_b += (r10*mask)*(u . v)
            #pragma unroll 2
            for (int b = 0; b < 8; b++) {
                const float* g = geo_s + b * 9;
                float mask = g[8];
                float r10 = rad_s[b * 160 + 96 + c] * mask;
                float r11 = rad_s[b * 160 + 128 + c] * mask;
                const float* v = p.in1 + ((size_t)(b0 + b) * 32 + c) * 3;
                float v0 = v[0], v1 = v[1], v2 = v[2];
                float ux = g[0], uy = g[1], uz = g[2];
                acc0 = fmaf(r11, uy * v2 - uz * v1, acc0);
                acc1 = fmaf(r11, uz * v0 - ux * v2, acc1);
                acc2 = fmaf(r11, ux * v1 - uy * v0, acc2);
                acc3 = fmaf(r10, ux * v0 + uy * v1 + uz * v2, acc3);
            }
        } else {
            // o1_a += (r01*mask) * u * x0
            #pragma unroll 2
            for (int b = 0; b < 8; b++) {
                const float* g = geo_s + b * 9;
                float r01 = rad_s[b * 160 + 32 + c] * g[8];
                float x0 = p.in0[(size_t)(b0 + b) * 32 + c];
                float rx = r01 * x0;
                acc0 = fmaf(rx, g[0], acc0);
                acc1 = fmaf(rx, g[1], acc1);
                acc2 = fmaf(rx, g[2], acc2);
            }
        }
    }

    // ---- epilogue: each warp writes its own components ----
    float* out = p.out;
    if (f == 0) {          // o2_s  [1,a,c,:] of o2 block
        size_t base = 180224 + (((size_t)(NNODES + a)) * 32 + c) * 5;
        out[base + 0] = acc0; out[base + 1] = acc1; out[base + 2] = acc2;
        out[base + 3] = acc3; out[base + 4] = acc4;
    } else if (f == 1) {   // o2_a  [0,a,c,:]
        size_t base = 180224 + (((size_t)a) * 32 + c) * 5;
        out[base + 0] = acc0; out[base + 1] = acc1; out[base + 2] = acc2;
        out[base + 3] = acc3; out[base + 4] = acc4;
    } else if (f == 2) {   // o1_s [1,...] + o0_s [0,...]
        size_t base = 32768 + (((size_t)(NNODES + a)) * 32 + c) * 3;
        out[base + 0] = acc0; out[base + 1] = acc1; out[base + 2] = acc2;
        out[(size_t)a * 32 + c] = acc3;
    } else if (f == 3) {   // o1_c [2,...] + o0_b [1,...]
        size_t base = 32768 + (((size_t)(2 * NNODES + a)) * 32 + c) * 3;
        out[base + 0] = acc0; out[base + 1] = acc1; out[base + 2] = acc2;
        out[16384 + (size_t)a * 32 + c] = acc3;
    } else {               // o1_a [0,...]
        size_t base = 32768 + (((size_t)a) * 32 + c) * 3;
        out[base + 0] = acc0; out[base + 1] = acc1; out[base + 2] = acc2;
    }
}

extern "C" void kernel_launch(void* const* d_in, const int* in_sizes, int n_in,
                              void* d_out, int out_size) {
    Params p;
    p.in0 = (const float*)d_in[0];
    p.in1 = (const float*)d_in[1];
    p.in2 = (const float*)d_in[2];
    p.rbf = (const float*)d_in[3];
    p.rij = (const float*)d_in[4];
    for (int f = 0; f < 5; f++) {
        p.w1[f] = (const float*)d_in[5 + 4 * f];
        p.b1[f] = (const float*)d_in[6 + 4 * f];
        p.w2[f] = (const float*)d_in[7 + 4 * f];
        p.b2[f] = (const float*)d_in[8 + 4 * f];
    }
    p.out = (float*)d_out;

    tfn_kernel<<<NNODES, 160>>>(p);
}